// round 11
// baseline (speedup 1.0000x reference)
#include <cuda_runtime.h>
#include <cstdint>

#define HWDIM 1024
#define NPIX  (HWDIM*HWDIM)
#define NSEG  5000
#define R1    1449
#define NR1   (R1*R1)
#define CROP  211
#define CB    25
#define TB    10
#define OUT_TOTAL 1600000

#define C45f 0.70710678118654752440f

// -------- device scratch (static; no runtime allocation) --------
__device__ float    v10_rotimg[3*NR1];     // +45-rotated image on full 1449^2 canvas
__device__ float    v10_gradrot[6*NR1];    // Scharr of rotated canvas, [c*2+g][NR1]
__device__ float    v10_gbase[6*NPIX];     // Scharr of original img,   [c*2+g][NPIX]
__device__ float    v10_grot[6*NPIX];      // back-rotated(-45) + crop[211:1235] of v10_gradrot
__device__ unsigned v10_mink[12], v10_maxk[12];  // raw-gradient plane min/max (orderable keys)
__device__ float    v10_nmin[24];          // per deriv-channel hmin
__device__ float    v10_nrcp[24];          // frcp_rn(hmax - hmin)  — XLA's hoisted reciprocal
__device__ int      v10_bx0[NSEG], v10_bx1[NSEG], v10_by0[NSEG], v10_by1[NSEG], v10_sz[NSEG];
__device__ int      v10_ch[NSEG*3*CB];
__device__ int      v10_th[NSEG*3*8*TB];
__device__ int      v10_w64;

// -------- helpers --------
__device__ __forceinline__ unsigned fkey(float f){
    unsigned u = __float_as_uint(f);
    return (u & 0x80000000u) ? ~u : (u | 0x80000000u);
}
__device__ __forceinline__ float unfkey(unsigned k){
    unsigned u = (k & 0x80000000u) ? (k ^ 0x80000000u) : ~k;
    return __uint_as_float(u);
}

// Scharr per reference (lax.conv = cross-correlation, zero pad, stride 1):
// k0 = [[-3,0,3],[10,0,10],[-3,0,3]],  k1 = k0^T.
__device__ __forceinline__ void scharr_pt(const float* __restrict__ p, int y, int x,
                                          int H, int W, float& G0, float& G1){
    const float* r = p + y*W + x;
    float a  = (y>0   && x>0  ) ? r[-W-1] : 0.f;
    float b  = (y>0           ) ? r[-W  ] : 0.f;
    float cc = (y>0   && x<W-1) ? r[-W+1] : 0.f;
    float d  = (         x>0  ) ? r[  -1] : 0.f;
    float e  = (         x<W-1) ? r[  +1] : 0.f;
    float f  = (y<H-1 && x>0  ) ? r[ W-1] : 0.f;
    float gg = (y<H-1         ) ? r[ W  ] : 0.f;
    float h  = (y<H-1 && x<W-1) ? r[ W+1] : 0.f;
    G0 = -3.f*a + 3.f*cc + 10.f*d + 10.f*e - 3.f*f + 3.f*h;
    G1 = -3.f*a + 10.f*b - 3.f*cc + 3.f*f  + 10.f*gg + 3.f*h;
}

// ==================== kernels ====================

__global__ void ss10_zero(){
    int i = blockIdx.x*blockDim.x + threadIdx.x;
    int stride = gridDim.x*blockDim.x;
    for (int j = i; j < NSEG*3*8*TB; j += stride) v10_th[j] = 0;
    for (int j = i; j < NSEG*3*CB;   j += stride) v10_ch[j] = 0;
    for (int j = i; j < NSEG; j += stride){
        v10_sz[j]  = 0;
        v10_bx0[j] = 0x7FFFFFFF; v10_by0[j] = 0x7FFFFFFF;
        v10_bx1[j] = (int)0x80000000; v10_by1[j] = (int)0x80000000;
    }
    if (i < 12){ v10_mink[i] = 0xFFFFFFFFu; v10_maxk[i] = 0u; }
    if (i == 0) v10_w64 = 1;
}

// int64-vs-int32 sniff on reg_lab (labels < 5000, so int64 high words are 0).
__global__ void ss10_dtype(const int* __restrict__ r32){
    int i = blockIdx.x*blockDim.x + threadIdx.x;    // 4096 threads
    if (r32[2*i+1] != 0) v10_w64 = 0;               // benign same-value race
}

// Stage 1: rotate img by +45 into 1449^2 canvas (nearest, round-half-even, zero fill).
__global__ void ss10_rot45(const float* __restrict__ img){
    int x = blockIdx.x*blockDim.x + threadIdx.x;
    int y = blockIdx.y;
    if (x >= R1) return;
    float dx = __fsub_rn((float)x, 724.0f);
    float dy = __fsub_rn((float)y, 724.0f);
    float t1 = __fmul_rn(C45f, dx);
    float t2 = __fmul_rn(C45f, dy);
    float sx = __fadd_rn(__fsub_rn(t1, t2), 511.5f);   // c*dx - s*dy + 511.5, s=+C45
    float sy = __fadd_rn(__fadd_rn(t1, t2), 511.5f);   // s*dx + c*dy + 511.5
    bool valid = (sx >= -0.5f) & (sx <= 1023.5f) & (sy >= -0.5f) & (sy <= 1023.5f);
    int ix = min(max((int)rintf(sx), 0), HWDIM-1);
    int iy = min(max((int)rintf(sy), 0), HWDIM-1);
    int src = iy*HWDIM + ix;
    int p = y*R1 + x;
    #pragma unroll
    for (int c = 0; c < 3; c++)
        v10_rotimg[c*NR1 + p] = valid ? __ldg(img + c*NPIX + src) : 0.f;
}

// Stage 2: Scharr over the entire rotated canvas, materialized (like the reference).
__global__ void ss10_scharr_rot(){
    int x = blockIdx.x*blockDim.x + threadIdx.x;
    int y = blockIdx.y;
    if (x >= R1) return;
    int p = y*R1 + x;
    #pragma unroll
    for (int c = 0; c < 3; c++){
        float G0, G1;
        scharr_pt(v10_rotimg + c*NR1, y, x, R1, R1, G0, G1);
        v10_gradrot[(2*c+0)*NR1 + p] = G0;
        v10_gradrot[(2*c+1)*NR1 + p] = G1;
    }
}

// Stage 3: Scharr of the original image, materialized.
__global__ void ss10_scharr_base(const float* __restrict__ img){
    int p = blockIdx.x*blockDim.x + threadIdx.x;    // exactly NPIX
    int x = p & (HWDIM-1), y = p >> 10;
    #pragma unroll
    for (int c = 0; c < 3; c++){
        float G0, G1;
        scharr_pt(img + c*NPIX, y, x, HWDIM, HWDIM, G0, G1);
        v10_gbase[(2*c+0)*NPIX + p] = G0;
        v10_gbase[(2*c+1)*NPIX + p] = G1;
    }
}

// Stage 4: pure gather — rotate gradients by -45 into the 2050^2 frame, keep crop [211:1235)^2.
__global__ void ss10_backrot(){
    int p = blockIdx.x*blockDim.x + threadIdx.x;    // exactly NPIX
    int x = p & (HWDIM-1), y = p >> 10;
    float dx = __fsub_rn((float)(x + CROP), 1024.5f);
    float dy = __fsub_rn((float)(y + CROP), 1024.5f);
    float t1 = __fmul_rn(C45f, dx);
    float t2 = __fmul_rn(C45f, dy);
    // angle=-45: c=+C45, s=-C45:  sx = c*dx - s*dy + 724 ; sy = s*dx + c*dy + 724
    float sx = __fadd_rn(__fadd_rn(t1, t2), 724.0f);
    float sy = __fadd_rn(__fsub_rn(t2, t1), 724.0f);
    bool valid = (sx >= -0.5f) & (sx <= 1448.5f) & (sy >= -0.5f) & (sy <= 1448.5f);
    int ix = min(max((int)rintf(sx), 0), R1-1);
    int iy = min(max((int)rintf(sy), 0), R1-1);
    int q = iy*R1 + ix;
    #pragma unroll
    for (int pl = 0; pl < 6; pl++)
        v10_grot[pl*NPIX + p] = valid ? __ldg(v10_gradrot + pl*NR1 + q) : 0.f;
}

// Stage 5: plane-wise min/max of the 6 base + 6 rotated-cropped gradient planes.
__global__ void ss10_minmax(){
    int p = blockIdx.x*blockDim.x + threadIdx.x;    // exactly NPIX
    float mn[12], mx[12];
    #pragma unroll
    for (int pl = 0; pl < 6; pl++){
        float vb = v10_gbase[pl*NPIX + p];
        float vr = v10_grot [pl*NPIX + p];
        mn[pl]   = mx[pl]   = vb;
        mn[6+pl] = mx[6+pl] = vr;
    }
    #pragma unroll
    for (int i = 0; i < 12; i++){
        #pragma unroll
        for (int off = 16; off; off >>= 1){
            mn[i] = fminf(mn[i], __shfl_xor_sync(0xFFFFFFFFu, mn[i], off));
            mx[i] = fmaxf(mx[i], __shfl_xor_sync(0xFFFFFFFFu, mx[i], off));
        }
    }
    if ((threadIdx.x & 31) == 0){
        #pragma unroll
        for (int i = 0; i < 12; i++){
            atomicMin(&v10_mink[i], fkey(mn[i]));
            atomicMax(&v10_maxk[i], fkey(mx[i]));
        }
    }
}

// Stage 6: normalization constants per deriv-channel.
// Channel order within each c: [g0+, g1+, g0-, g1-, r0+, r1+, r0-, r1-].
// KEY numerical point: XLA rewrites (x-hmin)/(hmax-hmin) into
// (x-hmin) * broadcast(1/(hmax-hmin)) with a correctly-rounded reciprocal.
// We store that reciprocal (frcp_rn) and MULTIPLY per pixel, matching bit-for-bit.
__global__ void ss10_norm(){
    int k = threadIdx.x;
    if (k >= 24) return;
    int c = k >> 3, ch = k & 7;
    int gd = ch & 1;
    bool isrot = ch >= 4;
    bool ispos = ((ch >> 1) & 1) == 0;
    int m = (isrot ? 6 : 0) + c*2 + gd;
    float gmin = unfkey(v10_mink[m]);
    float gmax = unfkey(v10_maxk[m]);
    float hmin, hmax;
    if (ispos){ hmin = fmaxf(gmin, 0.f); hmax = fmaxf(gmax, 0.f); }   // extrema of max(g,0)
    else      { hmin = fminf(gmin, 0.f); hmax = fminf(gmax, 0.f); }   // extrema of min(g,0)
    v10_nmin[k] = hmin;
    v10_nrcp[k] = __frcp_rn(__fsub_rn(hmax, hmin));   // XLA's hoisted 1/(hmax-hmin)
}

// Stage 7: per-pixel stats — bbox, size, color hist, texture hist.
__global__ void ss10_hist(const float* __restrict__ img, const void* __restrict__ reg){
    __shared__ float s_hmin[24], s_hr[24];
    if (threadIdx.x < 24){
        s_hmin[threadIdx.x] = v10_nmin[threadIdx.x];
        s_hr[threadIdx.x]   = v10_nrcp[threadIdx.x];
    }
    __syncthreads();

    int p = blockIdx.x*blockDim.x + threadIdx.x;    // exactly NPIX
    int x = p & (HWDIM-1), y = p >> 10;
    int s;
    if (v10_w64) s = (int)__ldg((const long long*)reg + p);
    else         s = __ldg((const int*)reg + p);
    if ((unsigned)s >= (unsigned)NSEG) return;      // defensive; never taken on valid data

    // Front-batch all per-pixel loads (MLP), then issue the atomics.
    float v[3], gb[6], gr[6];
    #pragma unroll
    for (int c = 0; c < 3; c++) v[c] = __ldg(img + c*NPIX + p);
    #pragma unroll
    for (int pl = 0; pl < 6; pl++){
        gb[pl] = __ldg(v10_gbase + pl*NPIX + p);
        gr[pl] = __ldg(v10_grot  + pl*NPIX + p);
    }

    atomicAdd(&v10_sz[s], 1);
    atomicMin(&v10_bx0[s], x);
    atomicMax(&v10_bx1[s], x);
    atomicMin(&v10_by0[s], y);
    atomicMax(&v10_by1[s], y);

    #pragma unroll
    for (int c = 0; c < 3; c++){
        int qc = (int)(v[c] * 24.0f);               // img in [0,1) -> bins [0,24]
        atomicAdd(&v10_ch[(s*3+c)*CB + qc], 1);

        float q0 = gb[2*c+0], q1 = gb[2*c+1];
        float r0 = gr[2*c+0], r1 = gr[2*c+1];
        float vals[8] = { fmaxf(q0,0.f), fmaxf(q1,0.f), fminf(q0,0.f), fminf(q1,0.f),
                          fmaxf(r0,0.f), fmaxf(r1,0.f), fminf(r0,0.f), fminf(r1,0.f) };
        #pragma unroll
        for (int ch = 0; ch < 8; ch++){
            int k = c*8 + ch;
            // XLA-exact: deriv = (x - hmin) * rcp ;  qt = trunc(deriv * 9).
            // NOTE: deriv for x==hmax is a*rcp(a) = 1 +/- 1ulp -> bin 8 OR 9 per channel,
            // exactly as the reference's reciprocal-multiply rewrite behaves.
            float deriv = __fmul_rn(__fsub_rn(vals[ch], s_hmin[k]), s_hr[k]);
            int qt = (int)__fmul_rn(deriv, 9.0f);
            qt = min(max(qt, 0), TB-1);
            atomicAdd(&v10_th[((s*3+c)*8 + ch)*TB + qt], 1);
        }
    }
}

// Stage 8: write outputs.
// Layout (float32): xywh (5000,4) | sizes (5000) | color (5000,3,25) | tex (5000,3,8,10)
// Normalizations use count * frcp_rn(denom) to match XLA's divide->reciprocal rewrite.
__global__ void ss10_out(float* __restrict__ out, int out_size){
    int i = blockIdx.x*blockDim.x + threadIdx.x;
    if (i >= OUT_TOTAL || i >= out_size) return;
    if (i < 20000){
        int s = i >> 2, j = i & 3;
        int v;
        if      (j == 0) v = v10_bx0[s];
        else if (j == 1) v = v10_by0[s];
        else if (j == 2) v = v10_bx1[s] - v10_bx0[s];
        else             v = v10_by1[s] - v10_by0[s];
        out[i] = (float)v;
    } else if (i < 25000){
        out[i] = (float)v10_sz[i - 20000];
    } else if (i < 400000){
        int j = i - 25000;
        int s = j / 75;
        float rcp = __frcp_rn(__fmul_rn(3.0f, (float)v10_sz[s]));
        out[i] = __fmul_rn((float)v10_ch[j], rcp);
    } else {
        int j = i - 400000;
        int s = j / 240;
        float rcp = __frcp_rn(__fmul_rn(24.0f, (float)v10_sz[s]));
        out[i] = __fmul_rn((float)v10_th[j], rcp);
    }
}

extern "C" void kernel_launch(void* const* d_in, const int* in_sizes, int n_in,
                              void* d_out, int out_size){
    const float* img = (const float*)d_in[0];
    const void*  reg = d_in[1];
    float* out = (float*)d_out;

    dim3 canvas_grid((R1 + 255)/256, R1);

    ss10_zero<<<2048, 256>>>();
    ss10_dtype<<<16, 256>>>((const int*)reg);
    ss10_rot45<<<canvas_grid, 256>>>(img);
    ss10_scharr_rot<<<canvas_grid, 256>>>();
    ss10_scharr_base<<<NPIX/256, 256>>>(img);
    ss10_backrot<<<NPIX/256, 256>>>();
    ss10_minmax<<<NPIX/256, 256>>>();
    ss10_norm<<<1, 32>>>();
    ss10_hist<<<NPIX/256, 256>>>(img, reg);
    ss10_out<<<(OUT_TOTAL + 255)/256, 256>>>(out, out_size);
}

// round 12
// speedup vs baseline: 1.1798x; 1.1798x over previous
#include <cuda_runtime.h>
#include <cstdint>

#define HWDIM 1024
#define NPIX  (HWDIM*HWDIM)
#define NSEG  5000
#define R1    1449
#define NR1   (R1*R1)
#define CROP  211
#define CB    25
#define TB    10
#define OUT_TOTAL 1600000

#define C45f 0.70710678118654752440f

// -------- device scratch (static; no runtime allocation) --------
__device__ float    v11_rotimg[3*NR1];      // +45-rotated image, 1449^2 per channel
__device__ float2   v11_gradrot[3*NR1];     // Scharr of rotated canvas, (G0,G1) packed per c
__device__ float2   v11_gbase[3*NPIX];      // Scharr of original img, (G0,G1) packed per c
__device__ float2   v11_grot[3*NPIX];       // back-rotated(-45)+cropped scharr, packed per c
__device__ unsigned v11_mink[12], v11_maxk[12];
__device__ float    v11_nmin[24], v11_nrcp[24];  // hmin, frcp_rn(hmax-hmin) per deriv channel
__device__ int      v11_tbin[24];           // bin of value 0.0 per deriv channel (constant bin)
__device__ int      v11_bx0[NSEG], v11_bx1[NSEG], v11_by0[NSEG], v11_by1[NSEG], v11_sz[NSEG];
__device__ int      v11_ch[NSEG*3*CB];
// texture hist: [s][c][pair(4)][bin(10)] as 32-bit words; low half = even channel, high = odd.
__device__ unsigned v11_th[NSEG*3*4*TB];
__device__ int      v11_w64;

// -------- helpers --------
__device__ __forceinline__ unsigned fkey(float f){
    unsigned u = __float_as_uint(f);
    return (u & 0x80000000u) ? ~u : (u | 0x80000000u);
}
__device__ __forceinline__ float unfkey(unsigned k){
    unsigned u = (k & 0x80000000u) ? (k ^ 0x80000000u) : ~k;
    return __uint_as_float(u);
}
// XLA-exact binning: deriv = (val - hmin) * rcp ; qt = trunc(deriv * 9), clamped.
__device__ __forceinline__ int binq(float val, float hmin, float rcp){
    float d = __fmul_rn(__fsub_rn(val, hmin), rcp);
    int q = (int)__fmul_rn(d, 9.0f);
    return min(max(q, 0), TB-1);
}

// Scharr per reference (lax.conv = cross-correlation, zero pad):
// k0 = [[-3,0,3],[10,0,10],[-3,0,3]], k1 = k0^T.
__device__ __forceinline__ void scharr_pt(const float* __restrict__ p, int y, int x,
                                          int H, int W, float& G0, float& G1){
    const float* r = p + y*W + x;
    float a  = (y>0   && x>0  ) ? r[-W-1] : 0.f;
    float b  = (y>0           ) ? r[-W  ] : 0.f;
    float cc = (y>0   && x<W-1) ? r[-W+1] : 0.f;
    float d  = (         x>0  ) ? r[  -1] : 0.f;
    float e  = (         x<W-1) ? r[  +1] : 0.f;
    float f  = (y<H-1 && x>0  ) ? r[ W-1] : 0.f;
    float gg = (y<H-1         ) ? r[ W  ] : 0.f;
    float h  = (y<H-1 && x<W-1) ? r[ W+1] : 0.f;
    G0 = -3.f*a + 3.f*cc + 10.f*d + 10.f*e - 3.f*f + 3.f*h;
    G1 = -3.f*a + 10.f*b - 3.f*cc + 3.f*f  + 10.f*gg + 3.f*h;
}

// warp-reduce 6 min/max lanes into global keys [koff..koff+6)
__device__ __forceinline__ void reduce6(float* mn, float* mx, int koff, int lane){
    #pragma unroll
    for (int i = 0; i < 6; i++){
        #pragma unroll
        for (int off = 16; off; off >>= 1){
            mn[i] = fminf(mn[i], __shfl_xor_sync(0xFFFFFFFFu, mn[i], off));
            mx[i] = fmaxf(mx[i], __shfl_xor_sync(0xFFFFFFFFu, mx[i], off));
        }
    }
    if (lane == 0){
        #pragma unroll
        for (int i = 0; i < 6; i++){
            atomicMin(&v11_mink[koff+i], fkey(mn[i]));
            atomicMax(&v11_maxk[koff+i], fkey(mx[i]));
        }
    }
}

// ==================== kernels ====================

__global__ void ss11_zero(){
    int i = blockIdx.x*blockDim.x + threadIdx.x;
    int stride = gridDim.x*blockDim.x;
    for (int j = i; j < NSEG*3*4*TB; j += stride) v11_th[j] = 0u;
    for (int j = i; j < NSEG*3*CB;   j += stride) v11_ch[j] = 0;
    for (int j = i; j < NSEG; j += stride){
        v11_bx0[j] = 0x7FFFFFFF; v11_by0[j] = 0x7FFFFFFF;
        v11_bx1[j] = (int)0x80000000; v11_by1[j] = (int)0x80000000;
    }
    if (i < 12){ v11_mink[i] = 0xFFFFFFFFu; v11_maxk[i] = 0u; }
    if (i == 0) v11_w64 = 1;
}

// int64-vs-int32 sniff on reg_lab (labels < 5000 -> int64 high words all zero).
__global__ void ss11_dtype(const int* __restrict__ r32){
    int i = blockIdx.x*blockDim.x + threadIdx.x;    // 4096 threads
    if (r32[2*i+1] != 0) v11_w64 = 0;               // benign same-value race
}

// rotate img by +45 into 1449^2 canvas (nearest, round-half-even, zero fill).
__global__ void ss11_rot45(const float* __restrict__ img){
    int x = blockIdx.x*blockDim.x + threadIdx.x;
    int y = blockIdx.y;
    if (x >= R1) return;
    float dx = __fsub_rn((float)x, 724.0f);
    float dy = __fsub_rn((float)y, 724.0f);
    float t1 = __fmul_rn(C45f, dx);
    float t2 = __fmul_rn(C45f, dy);
    float sx = __fadd_rn(__fsub_rn(t1, t2), 511.5f);
    float sy = __fadd_rn(__fadd_rn(t1, t2), 511.5f);
    bool valid = (sx >= -0.5f) & (sx <= 1023.5f) & (sy >= -0.5f) & (sy <= 1023.5f);
    int ix = min(max((int)rintf(sx), 0), HWDIM-1);
    int iy = min(max((int)rintf(sy), 0), HWDIM-1);
    int src = iy*HWDIM + ix;
    int p = y*R1 + x;
    #pragma unroll
    for (int c = 0; c < 3; c++)
        v11_rotimg[c*NR1 + p] = valid ? __ldg(img + c*NPIX + src) : 0.f;
}

// Scharr over the rotated canvas, materialized as float2.
__global__ void ss11_scharr_rot(){
    int x = blockIdx.x*blockDim.x + threadIdx.x;
    int y = blockIdx.y;
    if (x >= R1) return;
    int p = y*R1 + x;
    #pragma unroll
    for (int c = 0; c < 3; c++){
        float G0, G1;
        scharr_pt(v11_rotimg + c*NR1, y, x, R1, R1, G0, G1);
        v11_gradrot[c*NR1 + p] = make_float2(G0, G1);
    }
}

// Scharr of the original image (float2) + min/max of the 6 base planes (keys 0..5).
__global__ void ss11_scharr_base(const float* __restrict__ img){
    int p = blockIdx.x*blockDim.x + threadIdx.x;    // exactly NPIX
    int x = p & (HWDIM-1), y = p >> 10;
    float mn[6], mx[6];
    #pragma unroll
    for (int c = 0; c < 3; c++){
        float G0, G1;
        scharr_pt(img + c*NPIX, y, x, HWDIM, HWDIM, G0, G1);
        v11_gbase[c*NPIX + p] = make_float2(G0, G1);
        mn[2*c+0] = mx[2*c+0] = G0;
        mn[2*c+1] = mx[2*c+1] = G1;
    }
    reduce6(mn, mx, 0, threadIdx.x & 31);
}

// back-rotate(-45) + crop gather of gradrot (float2 loads) + min/max of rot planes (keys 6..11).
__global__ void ss11_backrot(){
    int p = blockIdx.x*blockDim.x + threadIdx.x;    // exactly NPIX
    int x = p & (HWDIM-1), y = p >> 10;
    float dx = __fsub_rn((float)(x + CROP), 1024.5f);
    float dy = __fsub_rn((float)(y + CROP), 1024.5f);
    float t1 = __fmul_rn(C45f, dx);
    float t2 = __fmul_rn(C45f, dy);
    float sx = __fadd_rn(__fadd_rn(t1, t2), 724.0f);
    float sy = __fadd_rn(__fsub_rn(t2, t1), 724.0f);
    bool valid = (sx >= -0.5f) & (sx <= 1448.5f) & (sy >= -0.5f) & (sy <= 1448.5f);
    int ix = min(max((int)rintf(sx), 0), R1-1);
    int iy = min(max((int)rintf(sy), 0), R1-1);
    int q = iy*R1 + ix;
    float mn[6], mx[6];
    #pragma unroll
    for (int c = 0; c < 3; c++){
        float2 g = valid ? __ldg(&v11_gradrot[c*NR1 + q]) : make_float2(0.f, 0.f);
        v11_grot[c*NPIX + p] = g;
        mn[2*c+0] = mx[2*c+0] = g.x;
        mn[2*c+1] = mx[2*c+1] = g.y;
    }
    reduce6(mn, mx, 6, threadIdx.x & 31);
}

// normalization constants + the constant bin of value 0.0 per channel.
// Channel order within each c: [g0+, g1+, g0-, g1-, r0+, r1+, r0-, r1-].
__global__ void ss11_norm(){
    int k = threadIdx.x;
    if (k >= 24) return;
    int c = k >> 3, ch = k & 7;
    int gd = ch & 1;
    bool isrot = ch >= 4;
    bool ispos = ((ch >> 1) & 1) == 0;
    int m = (isrot ? 6 : 0) + c*2 + gd;
    float gmin = unfkey(v11_mink[m]);
    float gmax = unfkey(v11_maxk[m]);
    float hmin, hmax;
    if (ispos){ hmin = fmaxf(gmin, 0.f); hmax = fmaxf(gmax, 0.f); }
    else      { hmin = fminf(gmin, 0.f); hmax = fminf(gmax, 0.f); }
    float rcp = __frcp_rn(__fsub_rn(hmax, hmin));   // XLA's hoisted 1/(hmax-hmin)
    v11_nmin[k] = hmin;
    v11_nrcp[k] = rcp;
    v11_tbin[k] = binq(0.0f, hmin, rcp);            // bin that value 0 falls into (exact same path)
}

// per-pixel stats: bbox + color hist + texture DATA bins only.
// For each gradient g: the relu-side channel with g==0 always lands in bin(0) (a per-channel
// constant) — that mass is reconstructed later as size - sum(data bins). So: 1 RED per nonzero
// gradient instead of 2 per gradient. 16-bit halves pack even/odd channels; same-sign same-bin
// pairs merge into a single +0x10001 RED.
__global__ void ss11_hist(const float* __restrict__ img, const void* __restrict__ reg){
    __shared__ float s_hmin[24], s_hr[24];
    if (threadIdx.x < 24){
        s_hmin[threadIdx.x] = v11_nmin[threadIdx.x];
        s_hr[threadIdx.x]   = v11_nrcp[threadIdx.x];
    }
    __syncthreads();

    int p = blockIdx.x*blockDim.x + threadIdx.x;    // exactly NPIX
    int x = p & (HWDIM-1), y = p >> 10;
    int s;
    if (v11_w64) s = (int)__ldg((const long long*)reg + p);
    else         s = __ldg((const int*)reg + p);
    if ((unsigned)s >= (unsigned)NSEG) return;      // defensive

    float v[3]; float2 gb[3], gr[3];
    #pragma unroll
    for (int c = 0; c < 3; c++){
        v[c]  = __ldg(img + c*NPIX + p);
        gb[c] = __ldg(&v11_gbase[c*NPIX + p]);
        gr[c] = __ldg(&v11_grot [c*NPIX + p]);
    }

    atomicMin(&v11_bx0[s], x);
    atomicMax(&v11_bx1[s], x);
    atomicMin(&v11_by0[s], y);
    atomicMax(&v11_by1[s], y);

    #pragma unroll
    for (int c = 0; c < 3; c++){
        int qc = (int)(v[c] * 24.0f);
        atomicAdd(&v11_ch[(s*3+c)*CB + qc], 1);

        unsigned bw = (unsigned)(s*3+c)*40u;        // 4 pairs * 10 bins per (s,c)
        #pragma unroll
        for (int gi = 0; gi < 2; gi++){             // gi=0: base grads (ch 0..3), gi=1: rot (ch 4..7)
            float A = gi ? gr[c].x : gb[c].x;       // grad 0 -> channels {off+0 (pos), off+2 (neg)}
            float B = gi ? gr[c].y : gb[c].y;       // grad 1 -> channels {off+1 (pos), off+3 (neg)}
            int off = gi*4;
            int wA = -1, wB = -1;
            if (A != 0.f){
                int ch = off + ((A > 0.f) ? 0 : 2);
                int k = c*8 + ch;
                wA = (int)bw + (ch>>1)*10 + binq(A, s_hmin[k], s_hr[k]);
            }
            if (B != 0.f){
                int ch = off + ((B > 0.f) ? 1 : 3);
                int k = c*8 + ch;
                wB = (int)bw + (ch>>1)*10 + binq(B, s_hmin[k], s_hr[k]);
            }
            if (wA >= 0 && wA == wB) atomicAdd(&v11_th[wA], 0x10001u);
            else {
                if (wA >= 0) atomicAdd(&v11_th[wA], 1u);
                if (wB >= 0) atomicAdd(&v11_th[wB], 0x10000u);
            }
        }
    }
}

// region sizes derived exactly from color counts (each pixel adds exactly 3 color counts).
__global__ void ss11_sizes(){
    int s = blockIdx.x*blockDim.x + threadIdx.x;
    if (s >= NSEG) return;
    int t = 0;
    #pragma unroll 5
    for (int j = 0; j < 3*CB; j++) t += __ldg(v11_ch + s*3*CB + j);
    v11_sz[s] = t / 3;
}

// add the deferred constant-bin mass: per (s,c,pair,half): missing = size - sum(data bins),
// added at tbin[channel]. Exclusive ownership per thread -> plain RMW, no atomics.
__global__ void ss11_corr(){
    int t = blockIdx.x*blockDim.x + threadIdx.x;    // NSEG*12 threads
    if (t >= NSEG*12) return;
    int s = t / 12, cp = t % 12;
    int c = cp >> 2, pr = cp & 3;
    unsigned base = (unsigned)(s*3+c)*40u + pr*10;
    unsigned w[TB];
    int sum0 = 0, sum1 = 0;
    #pragma unroll
    for (int b = 0; b < TB; b++){
        w[b] = v11_th[base + b];
        sum0 += (int)(w[b] & 0xFFFFu);
        sum1 += (int)(w[b] >> 16);
    }
    int size = v11_sz[s];
    int t0 = v11_tbin[c*8 + pr*2 + 0];
    int t1 = v11_tbin[c*8 + pr*2 + 1];
    w[t0] += (unsigned)(size - sum0);
    w[t1] += (unsigned)(size - sum1) << 16;
    v11_th[base + t0] = w[t0];
    if (t1 != t0) v11_th[base + t1] = w[t1];
}

// outputs: xywh (5000,4) | sizes (5000) | color (5000,3,25) | tex (5000,3,8,10)
// normalizations: count * frcp_rn(denom), matching XLA's divide->reciprocal rewrite.
__global__ void ss11_out(float* __restrict__ out, int out_size){
    int i = blockIdx.x*blockDim.x + threadIdx.x;
    if (i >= OUT_TOTAL || i >= out_size) return;
    if (i < 20000){
        int s = i >> 2, j = i & 3;
        int v;
        if      (j == 0) v = v11_bx0[s];
        else if (j == 1) v = v11_by0[s];
        else if (j == 2) v = v11_bx1[s] - v11_bx0[s];
        else             v = v11_by1[s] - v11_by0[s];
        out[i] = (float)v;
    } else if (i < 25000){
        out[i] = (float)v11_sz[i - 20000];
    } else if (i < 400000){
        int j = i - 25000;
        int s = j / 75;
        float rcp = __frcp_rn(__fmul_rn(3.0f, (float)v11_sz[s]));
        out[i] = __fmul_rn((float)v11_ch[j], rcp);
    } else {
        int j = i - 400000;
        int s = j / 240;
        int r = j % 240;
        int c = r / 80;  r %= 80;
        int ch = r / 10; int b = r % 10;
        unsigned w = v11_th[(unsigned)(s*3+c)*40u + (ch>>1)*10 + b];
        int cnt = (int)((w >> (16*(ch & 1))) & 0xFFFFu);
        float rcp = __frcp_rn(__fmul_rn(24.0f, (float)v11_sz[s]));
        out[i] = __fmul_rn((float)cnt, rcp);
    }
}

extern "C" void kernel_launch(void* const* d_in, const int* in_sizes, int n_in,
                              void* d_out, int out_size){
    const float* img = (const float*)d_in[0];
    const void*  reg = d_in[1];
    float* out = (float*)d_out;

    dim3 canvas_grid((R1 + 255)/256, R1);

    ss11_zero<<<2048, 256>>>();
    ss11_dtype<<<16, 256>>>((const int*)reg);
    ss11_rot45<<<canvas_grid, 256>>>(img);
    ss11_scharr_rot<<<canvas_grid, 256>>>();
    ss11_scharr_base<<<NPIX/256, 256>>>(img);
    ss11_backrot<<<NPIX/256, 256>>>();
    ss11_norm<<<1, 32>>>();
    ss11_hist<<<NPIX/256, 256>>>(img, reg);
    ss11_sizes<<<(NSEG + 255)/256, 256>>>();
    ss11_corr<<<(NSEG*12 + 255)/256, 256>>>();
    ss11_out<<<(OUT_TOTAL + 255)/256, 256>>>(out, out_size);
}